// round 6
// baseline (speedup 1.0000x reference)
#include <cuda_runtime.h>
#include <cuda_fp16.h>
#include <cstdint>

#define DEV __device__ __forceinline__

static constexpr int NROWS = 2048;
static constexpr int INF   = 4096;
static constexpr int OUTF  = 4096;

static constexpr int BM = 128, BN = 128, BK = 32;
static constexpr int STAGES = 4;
static constexpr int NIT = INF / BK;                     // 128
static constexpr int PITCH_H = 40;                       // halfs per smem row (32 + 8 pad)
static constexpr int PITCH_B = PITCH_H * 2;              // 80 bytes
static constexpr int A_BYTES = BM * PITCH_B;             // 10240
static constexpr int B_BYTES = BN * PITCH_B;             // 10240
static constexpr int STAGE_BYTES = A_BYTES + B_BYTES;    // 20480
static constexpr int SMEM_ALLOC = STAGES * STAGE_BYTES;  // 81920

// ---------------- scratch (no allocs allowed) ----------------
__device__ __align__(1024) __half g_wmean[(size_t)OUTF * INF];
__device__ __align__(1024) __half g_wvar [(size_t)OUTF * INF];
__device__ __align__(1024) __half g_xh   [(size_t)NROWS * INF];
__device__ __align__(1024) __half g_x2h  [(size_t)NROWS * INF];
__device__ float g_bmean[OUTF];
__device__ float g_bvar [OUTF];

// ---------------- PTX helpers ----------------
DEV uint32_t smem_u32(const void* p) {
    uint32_t a;
    asm("{ .reg .u64 t; cvta.to.shared.u64 t, %1; cvt.u32.u64 %0, t; }" : "=r"(a) : "l"(p));
    return a;
}
DEV void cp16(uint32_t saddr, const void* g) {
    asm volatile("cp.async.cg.shared.global [%0], [%1], 16;" :: "r"(saddr), "l"(g) : "memory");
}
DEV void ldm_x4(uint32_t* r, uint32_t addr) {
    asm volatile("ldmatrix.sync.aligned.m8n8.x4.shared.b16 {%0,%1,%2,%3}, [%4];"
                 : "=r"(r[0]), "=r"(r[1]), "=r"(r[2]), "=r"(r[3]) : "r"(addr));
}
DEV void mma16816(float* c, const uint32_t* a, uint32_t b0, uint32_t b1) {
    asm volatile(
        "mma.sync.aligned.m16n8k16.row.col.f32.f16.f16.f32 "
        "{%0,%1,%2,%3}, {%4,%5,%6,%7}, {%8,%9}, {%0,%1,%2,%3};"
        : "+f"(c[0]), "+f"(c[1]), "+f"(c[2]), "+f"(c[3])
        : "r"(a[0]), "r"(a[1]), "r"(a[2]), "r"(a[3]), "r"(b0), "r"(b1));
}

// ---------------- preprocessing ----------------
DEV void moments(float l0, float l1, float l2, float& mean, float& var) {
    float e0 = __expf(l0), e1 = __expf(l1), e2 = __expf(l2);
    float inv = 1.0f / (e0 + e1 + e2);
    float m  = (e2 - e0) * inv;
    float sq = (e2 + e0) * inv;
    mean = m;
    var  = sq - m * m;
}

__global__ void prep_w_kernel(const float* __restrict__ W) {
    const size_t P = (size_t)OUTF * INF;
    size_t i = ((size_t)blockIdx.x * blockDim.x + threadIdx.x) * 4;
    if (i >= P) return;
    float4 a = *(const float4*)(W + i);
    float4 b = *(const float4*)(W + P + i);
    float4 c = *(const float4*)(W + 2 * P + i);
    float m[4], v[4];
    moments(a.x, b.x, c.x, m[0], v[0]);
    moments(a.y, b.y, c.y, m[1], v[1]);
    moments(a.z, b.z, c.z, m[2], v[2]);
    moments(a.w, b.w, c.w, m[3], v[3]);
    __half2* pm = (__half2*)(g_wmean + i);
    pm[0] = __floats2half2_rn(m[0], m[1]);
    pm[1] = __floats2half2_rn(m[2], m[3]);
    __half2* pv = (__half2*)(g_wvar + i);
    pv[0] = __floats2half2_rn(v[0], v[1]);
    pv[1] = __floats2half2_rn(v[2], v[3]);
}

__global__ void prep_x_kernel(const float* __restrict__ x) {
    const size_t P = (size_t)NROWS * INF;
    size_t i = ((size_t)blockIdx.x * blockDim.x + threadIdx.x) * 4;
    if (i >= P) return;
    float4 a = *(const float4*)(x + i);
    __half2* ph = (__half2*)(g_xh + i);
    ph[0] = __floats2half2_rn(a.x, a.y);
    ph[1] = __floats2half2_rn(a.z, a.w);
    __half2* p2 = (__half2*)(g_x2h + i);
    p2[0] = __floats2half2_rn(a.x * a.x, a.y * a.y);
    p2[1] = __floats2half2_rn(a.z * a.z, a.w * a.w);
}

__global__ void prep_b_kernel(const float* __restrict__ B) {
    int o = blockIdx.x * blockDim.x + threadIdx.x;
    if (o >= OUTF) return;
    float m, v;
    moments(B[o], B[OUTF + o], B[2 * OUTF + o], m, v);
    g_bmean[o] = m;
    g_bvar[o]  = v;
}

// ---------------- GEMM ----------------
DEV void load_stage(char* smem, const char* gA, const char* gB, int cc, int tid) {
    char* sa  = smem + (cc & (STAGES - 1)) * STAGE_BYTES;
    char* sbt = sa + A_BYTES;
    const char* ga = gA + (size_t)cc * (BK * 2);
    const char* gb = gB + (size_t)cc * (BK * 2);
#pragma unroll
    for (int i = 0; i < 2; i++) {
        int idx = tid + i * 256;              // 0..511 over (row, 16B-seg)
        int row = idx >> 2, seg = idx & 3;
        uint32_t so = (uint32_t)(row * PITCH_B + seg * 16);
        size_t   go = (size_t)row * (INF * 2) + (size_t)seg * 16;
        cp16(smem_u32(sa  + so), ga + go);
        cp16(smem_u32(sbt + so), gb + go);
    }
}

__global__ void __launch_bounds__(256, 2)
gemm_kernel(float* __restrict__ out) {
    extern __shared__ char smem[];

    const int tid  = threadIdx.x;
    const int wid  = tid >> 5, lane = tid & 31;
    const int bn = blockIdx.x, bm = blockIdx.y, bz = blockIdx.z;

    const int wm = wid >> 1, wn = wid & 1;    // 4 x 2 warp grid
    const int m0 = wm * 32, n0 = wn * 64;     // warp tile 32 x 64

    const char* gA = (const char*)((bz == 0 ? g_xh    : g_x2h ) + (size_t)bm * BM * INF);
    const char* gB = (const char*)((bz == 0 ? g_wmean : g_wvar) + (size_t)bn * BN * INF);
    const float* bias = (bz == 0 ? g_bmean : g_bvar);

    float acc[2][8][4];
#pragma unroll
    for (int i = 0; i < 2; i++)
#pragma unroll
        for (int j = 0; j < 8; j++)
#pragma unroll
            for (int k = 0; k < 4; k++) acc[i][j][k] = 0.0f;

    // lane-dependent ldmatrix address offsets (bytes within a stage tile)
    const uint32_t a_off = (uint32_t)((m0 + (lane & 15)) * PITCH_B + (lane >> 4) * 16);
    const uint32_t b_off = (uint32_t)(A_BYTES + (n0 + (lane & 7) + ((lane >> 4) & 1) * 8) * PITCH_B
                                      + ((lane >> 3) & 1) * 16);
    const uint32_t smem_base = smem_u32(smem);

    // double-buffered register fragments
    uint32_t afr[2][2][4];
    uint32_t bfr[2][4][4];

    // prologue: stages 0..2 in flight
#pragma unroll
    for (int cc = 0; cc < STAGES - 1; cc++) {
        load_stage(smem, gA, gB, cc, tid);
        asm volatile("cp.async.commit_group;" ::: "memory");
    }
    // stages 0 and 1 complete (all but the newest group)
    asm volatile("cp.async.wait_group 1;" ::: "memory");
    __syncthreads();

    // fragments for (stage 0, k-step 0) into buffer 0
#pragma unroll
    for (int mb = 0; mb < 2; mb++)
        ldm_x4(afr[0][mb], smem_base + a_off + (uint32_t)(mb * 16 * PITCH_B));
#pragma unroll
    for (int nb = 0; nb < 4; nb++)
        ldm_x4(bfr[0][nb], smem_base + b_off + (uint32_t)(nb * 16 * PITCH_B));

#pragma unroll 1
    for (int it = 0; it < NIT; it++) {
        // ---- single sync point per iteration, BEFORE all MMA work ----
        // At this point it+3 groups are committed; wait_group 1 => stages
        // 0..it+1 complete; barrier makes them cross-thread visible AND
        // protects the overwrite of stage (it-1)&3 below (its last reader
        // was the buf1 ldmatrix in iteration it-1).
        asm volatile("cp.async.wait_group 1;" ::: "memory");
        __syncthreads();

        const int cc = it + STAGES - 1;
        if (cc < NIT) load_stage(smem, gA, gB, cc, tid);
        asm volatile("cp.async.commit_group;" ::: "memory");

        const uint32_t sa_u = smem_base + (uint32_t)((it & (STAGES - 1)) * STAGE_BYTES);
        const uint32_t nx_u = smem_base + (uint32_t)(((it + 1) & (STAGES - 1)) * STAGE_BYTES);

        // k-step 1 fragments of current stage into buf1
#pragma unroll
        for (int mb = 0; mb < 2; mb++)
            ldm_x4(afr[1][mb], sa_u + a_off + (uint32_t)(mb * 16 * PITCH_B + 32));
#pragma unroll
        for (int nb = 0; nb < 4; nb++)
            ldm_x4(bfr[1][nb], sa_u + b_off + (uint32_t)(nb * 16 * PITCH_B + 32));

        // MMA on buf0 (k-step 0) — overlaps the buf1 ldmatrix latency
#pragma unroll
        for (int mb = 0; mb < 2; mb++)
#pragma unroll
            for (int nb = 0; nb < 4; nb++) {
                mma16816(acc[mb][2 * nb],     afr[0][mb], bfr[0][nb][0], bfr[0][nb][1]);
                mma16816(acc[mb][2 * nb + 1], afr[0][mb], bfr[0][nb][2], bfr[0][nb][3]);
            }

        // next stage (it+1) k-step 0 fragments into buf0 — stage it+1 is
        // already complete+visible from this iteration's wait+sync.
#pragma unroll
        for (int mb = 0; mb < 2; mb++)
            ldm_x4(afr[0][mb], nx_u + a_off + (uint32_t)(mb * 16 * PITCH_B));
#pragma unroll
        for (int nb = 0; nb < 4; nb++)
            ldm_x4(bfr[0][nb], nx_u + b_off + (uint32_t)(nb * 16 * PITCH_B));

        // MMA on buf1 (k-step 1) — no barrier between operands and use;
        // these drain in the tensor pipe across next iteration's wait+sync.
#pragma unroll
        for (int mb = 0; mb < 2; mb++)
#pragma unroll
            for (int nb = 0; nb < 4; nb++) {
                mma16816(acc[mb][2 * nb],     afr[1][mb], bfr[1][nb][0], bfr[1][nb][1]);
                mma16816(acc[mb][2 * nb + 1], afr[1][mb], bfr[1][nb][2], bfr[1][nb][3]);
            }
    }

    // epilogue: direct float2 stores with bias
    const int qr = lane >> 2, qc = lane & 3;
    const size_t row_stride = 2 * (size_t)OUTF;
#pragma unroll
    for (int mf = 0; mf < 2; mf++) {
        const int gm = bm * BM + m0 + mf * 16 + qr;
#pragma unroll
        for (int nf = 0; nf < 8; nf++) {
            const int gn = bn * BN + n0 + nf * 8 + qc * 2;
            const float2 bv = *(const float2*)(bias + gn);
            float* p0 = out + (size_t)gm * row_stride + (size_t)bz * OUTF + gn;
            float* p1 = p0 + 8 * row_stride;
            float2 v0 = { acc[mf][nf][0] + bv.x, acc[mf][nf][1] + bv.y };
            float2 v1 = { acc[mf][nf][2] + bv.x, acc[mf][nf][3] + bv.y };
            *(float2*)p0 = v0;
            *(float2*)p1 = v1;
        }
    }
}

// ---------------- launch ----------------
extern "C" void kernel_launch(void* const* d_in, const int* in_sizes, int n_in,
                              void* d_out, int out_size) {
    const float *x = nullptr, *W = nullptr, *Bl = nullptr;
    for (int i = 0; i < n_in; i++) {
        long long s = in_sizes[i];
        if (s == (long long)NROWS * INF)          x  = (const float*)d_in[i];
        else if (s == 3LL * OUTF * INF)           W  = (const float*)d_in[i];
        else if (s == 3LL * OUTF)                 Bl = (const float*)d_in[i];
    }
    float* out = (float*)d_out;

    prep_w_kernel<<<(unsigned)(((size_t)OUTF * INF / 4 + 255) / 256), 256>>>(W);
    prep_x_kernel<<<(unsigned)(((size_t)NROWS * INF / 4 + 255) / 256), 256>>>(x);
    prep_b_kernel<<<(OUTF + 255) / 256, 256>>>(Bl);

    cudaFuncSetAttribute(gemm_kernel, cudaFuncAttributeMaxDynamicSharedMemorySize, SMEM_ALLOC);
    dim3 grid(OUTF / BN, NROWS / BM, 2);  // (32, 16, 2) = 1024 CTAs
    gemm_kernel<<<grid, 256, SMEM_ALLOC>>>(out);
}

// round 7
// speedup vs baseline: 1.0177x; 1.0177x over previous
#include <cuda_runtime.h>
#include <cuda_fp16.h>
#include <cstdint>

#define DEV __device__ __forceinline__

static constexpr int NROWS = 2048;
static constexpr int INF   = 4096;
static constexpr int OUTF  = 4096;

static constexpr int BM = 128, BN = 128, BK = 32;
static constexpr int STAGES = 5;                         // 5-deep ring
static constexpr int NIT = INF / BK;                     // 128 (64 pairs)
static constexpr int PITCH_H = 40;                       // halfs per smem row (32 + 8 pad)
static constexpr int PITCH_B = PITCH_H * 2;              // 80 bytes
static constexpr int A_BYTES = BM * PITCH_B;             // 10240
static constexpr int B_BYTES = BN * PITCH_B;             // 10240
static constexpr int STAGE_BYTES = A_BYTES + B_BYTES;    // 20480
static constexpr int SMEM_ALLOC = STAGES * STAGE_BYTES;  // 102400 (x2 CTAs = 200KB < 228KB)

// ---------------- scratch (no allocs allowed) ----------------
__device__ __align__(1024) __half g_wmean[(size_t)OUTF * INF];
__device__ __align__(1024) __half g_wvar [(size_t)OUTF * INF];
__device__ __align__(1024) __half g_xh   [(size_t)NROWS * INF];
__device__ __align__(1024) __half g_x2h  [(size_t)NROWS * INF];
__device__ float g_bmean[OUTF];
__device__ float g_bvar [OUTF];

// ---------------- PTX helpers ----------------
DEV uint32_t smem_u32(const void* p) {
    uint32_t a;
    asm("{ .reg .u64 t; cvta.to.shared.u64 t, %1; cvt.u32.u64 %0, t; }" : "=r"(a) : "l"(p));
    return a;
}
DEV void cp16(uint32_t saddr, const void* g) {
    asm volatile("cp.async.cg.shared.global [%0], [%1], 16;" :: "r"(saddr), "l"(g) : "memory");
}
DEV void ldm_x4(uint32_t* r, uint32_t addr) {
    asm volatile("ldmatrix.sync.aligned.m8n8.x4.shared.b16 {%0,%1,%2,%3}, [%4];"
                 : "=r"(r[0]), "=r"(r[1]), "=r"(r[2]), "=r"(r[3]) : "r"(addr));
}
DEV void mma16816(float* c, const uint32_t* a, uint32_t b0, uint32_t b1) {
    asm volatile(
        "mma.sync.aligned.m16n8k16.row.col.f32.f16.f16.f32 "
        "{%0,%1,%2,%3}, {%4,%5,%6,%7}, {%8,%9}, {%0,%1,%2,%3};"
        : "+f"(c[0]), "+f"(c[1]), "+f"(c[2]), "+f"(c[3])
        : "r"(a[0]), "r"(a[1]), "r"(a[2]), "r"(a[3]), "r"(b0), "r"(b1));
}

// ---------------- preprocessing ----------------
DEV void moments(float l0, float l1, float l2, float& mean, float& var) {
    float e0 = __expf(l0), e1 = __expf(l1), e2 = __expf(l2);
    float inv = 1.0f / (e0 + e1 + e2);
    float m  = (e2 - e0) * inv;
    float sq = (e2 + e0) * inv;
    mean = m;
    var  = sq - m * m;
}

__global__ void prep_w_kernel(const float* __restrict__ W) {
    const size_t P = (size_t)OUTF * INF;
    size_t i = ((size_t)blockIdx.x * blockDim.x + threadIdx.x) * 4;
    if (i >= P) return;
    float4 a = *(const float4*)(W + i);
    float4 b = *(const float4*)(W + P + i);
    float4 c = *(const float4*)(W + 2 * P + i);
    float m[4], v[4];
    moments(a.x, b.x, c.x, m[0], v[0]);
    moments(a.y, b.y, c.y, m[1], v[1]);
    moments(a.z, b.z, c.z, m[2], v[2]);
    moments(a.w, b.w, c.w, m[3], v[3]);
    __half2* pm = (__half2*)(g_wmean + i);
    pm[0] = __floats2half2_rn(m[0], m[1]);
    pm[1] = __floats2half2_rn(m[2], m[3]);
    __half2* pv = (__half2*)(g_wvar + i);
    pv[0] = __floats2half2_rn(v[0], v[1]);
    pv[1] = __floats2half2_rn(v[2], v[3]);
}

__global__ void prep_x_kernel(const float* __restrict__ x) {
    const size_t P = (size_t)NROWS * INF;
    size_t i = ((size_t)blockIdx.x * blockDim.x + threadIdx.x) * 4;
    if (i >= P) return;
    float4 a = *(const float4*)(x + i);
    __half2* ph = (__half2*)(g_xh + i);
    ph[0] = __floats2half2_rn(a.x, a.y);
    ph[1] = __floats2half2_rn(a.z, a.w);
    __half2* p2 = (__half2*)(g_x2h + i);
    p2[0] = __floats2half2_rn(a.x * a.x, a.y * a.y);
    p2[1] = __floats2half2_rn(a.z * a.z, a.w * a.w);
}

__global__ void prep_b_kernel(const float* __restrict__ B) {
    int o = blockIdx.x * blockDim.x + threadIdx.x;
    if (o >= OUTF) return;
    float m, v;
    moments(B[o], B[OUTF + o], B[2 * OUTF + o], m, v);
    g_bmean[o] = m;
    g_bvar[o]  = v;
}

// ---------------- GEMM ----------------
DEV void load_stage(char* smem, const char* gA, const char* gB, int cc, int tid) {
    char* sa  = smem + (cc % STAGES) * STAGE_BYTES;
    char* sbt = sa + A_BYTES;
    const char* ga = gA + (size_t)cc * (BK * 2);
    const char* gb = gB + (size_t)cc * (BK * 2);
#pragma unroll
    for (int i = 0; i < 2; i++) {
        int idx = tid + i * 256;              // 0..511 over (row, 16B-seg)
        int row = idx >> 2, seg = idx & 3;
        uint32_t so = (uint32_t)(row * PITCH_B + seg * 16);
        size_t   go = (size_t)row * (INF * 2) + (size_t)seg * 16;
        cp16(smem_u32(sa  + so), ga + go);
        cp16(smem_u32(sbt + so), gb + go);
    }
}

__global__ void __launch_bounds__(256, 2)
gemm_kernel(float* __restrict__ out) {
    extern __shared__ char smem[];

    const int tid  = threadIdx.x;
    const int wid  = tid >> 5, lane = tid & 31;
    const int bn = blockIdx.x, bm = blockIdx.y, bz = blockIdx.z;

    const int wm = wid >> 1, wn = wid & 1;    // 4 x 2 warp grid
    const int m0 = wm * 32, n0 = wn * 64;     // warp tile 32 x 64

    const char* gA = (const char*)((bz == 0 ? g_xh    : g_x2h ) + (size_t)bm * BM * INF);
    const char* gB = (const char*)((bz == 0 ? g_wmean : g_wvar) + (size_t)bn * BN * INF);
    const float* bias = (bz == 0 ? g_bmean : g_bvar);

    float acc[2][8][4];
#pragma unroll
    for (int i = 0; i < 2; i++)
#pragma unroll
        for (int j = 0; j < 8; j++)
#pragma unroll
            for (int k = 0; k < 4; k++) acc[i][j][k] = 0.0f;

    // lane-dependent ldmatrix address offsets (bytes within a stage tile)
    const uint32_t a_off = (uint32_t)((m0 + (lane & 15)) * PITCH_B + (lane >> 4) * 16);
    const uint32_t b_off = (uint32_t)(A_BYTES + (n0 + (lane & 7) + ((lane >> 4) & 1) * 8) * PITCH_B
                                      + ((lane >> 3) & 1) * 16);
    const uint32_t smem_base = smem_u32(smem);

    // double-buffered register fragments
    uint32_t afr[2][2][4];
    uint32_t bfr[2][4][4];

#define LOAD_A_FRAGS(buf, stage_u, koff)                                          \
    _Pragma("unroll")                                                             \
    for (int mb = 0; mb < 2; mb++)                                                \
        ldm_x4(afr[buf][mb], (stage_u) + a_off + (uint32_t)(mb * 16 * PITCH_B + (koff)));
#define LOAD_B_FRAGS(buf, stage_u, koff)                                          \
    _Pragma("unroll")                                                             \
    for (int nb = 0; nb < 4; nb++)                                                \
        ldm_x4(bfr[buf][nb], (stage_u) + b_off + (uint32_t)(nb * 16 * PITCH_B + (koff)));
#define MMA_BURST(buf)                                                            \
    _Pragma("unroll")                                                             \
    for (int mb = 0; mb < 2; mb++)                                                \
        _Pragma("unroll")                                                         \
        for (int nb = 0; nb < 4; nb++) {                                          \
            mma16816(acc[mb][2 * nb],     afr[buf][mb], bfr[buf][nb][0], bfr[buf][nb][1]); \
            mma16816(acc[mb][2 * nb + 1], afr[buf][mb], bfr[buf][nb][2], bfr[buf][nb][3]); \
        }

    // prologue: stages 0,1 (group G0) and 2,3 (group G1)
    load_stage(smem, gA, gB, 0, tid);
    load_stage(smem, gA, gB, 1, tid);
    asm volatile("cp.async.commit_group;" ::: "memory");
    load_stage(smem, gA, gB, 2, tid);
    load_stage(smem, gA, gB, 3, tid);
    asm volatile("cp.async.commit_group;" ::: "memory");
    asm volatile("cp.async.wait_group 1;" ::: "memory");   // G0 done: stages 0,1
    __syncthreads();

    // buf0 <- stage 0, k-step 0
    LOAD_A_FRAGS(0, smem_base, 0)
    LOAD_B_FRAGS(0, smem_base, 0)

#pragma unroll 1
    for (int p = 0; p < NIT; p += 2) {
        const uint32_t s0 = smem_base + (uint32_t)((p % STAGES) * STAGE_BYTES);        // stage p
        const uint32_t s1 = smem_base + (uint32_t)(((p + 1) % STAGES) * STAGE_BYTES);  // stage p+1
        const uint32_t s2 = smem_base + (uint32_t)(((p + 2) % STAGES) * STAGE_BYTES);  // stage p+2

        // stage p, k1 -> buf1 ; MMA k0 (buf0)
        LOAD_A_FRAGS(1, s0, 32)
        LOAD_B_FRAGS(1, s0, 32)
        MMA_BURST(0)

        // stage p+1, k0 -> buf0 ; MMA stage p k1 (buf1)
        LOAD_A_FRAGS(0, s1, 0)
        LOAD_B_FRAGS(0, s1, 0)
        MMA_BURST(1)

        // stage p+1, k1 -> buf1 ; MMA stage p+1 k0 (buf0)
        LOAD_A_FRAGS(1, s1, 32)
        LOAD_B_FRAGS(1, s1, 32)
        MMA_BURST(0)

        // refill: slot (p+4)%5 — its stage (p-1) was last read before the
        // previous pair's barrier -> safe to write pre-barrier.
        if (p + 4 < NIT) load_stage(smem, gA, gB, p + 4, tid);

        // drain committed groups (newest is pair p-2's {p+2,p+3}, issued a
        // full pair ago) -> stages p+2, p+3 resident; uncommitted p+4 loads
        // keep the memory pipe busy across the wait.
        asm volatile("cp.async.wait_group 0;" ::: "memory");
        __syncthreads();

        // slot (p+5)%5 == p%5: stage p's last reads were pre-barrier -> safe now.
        if (p + 5 < NIT) load_stage(smem, gA, gB, p + 5, tid);
        asm volatile("cp.async.commit_group;" ::: "memory");

        // stage p+2, k0 -> buf0 (resident; slot untouched by this pair's
        // writes) ; MMA stage p+1 k1 (buf1). Tail pair reads stale smem into
        // buf0 harmlessly (never consumed).
        LOAD_A_FRAGS(0, s2, 0)
        LOAD_B_FRAGS(0, s2, 0)
        MMA_BURST(1)
    }

    // epilogue: direct float2 stores with bias
    const int qr = lane >> 2, qc = lane & 3;
    const size_t row_stride = 2 * (size_t)OUTF;
#pragma unroll
    for (int mf = 0; mf < 2; mf++) {
        const int gm = bm * BM + m0 + mf * 16 + qr;
#pragma unroll
        for (int nf = 0; nf < 8; nf++) {
            const int gn = bn * BN + n0 + nf * 8 + qc * 2;
            const float2 bv = *(const float2*)(bias + gn);
            float* p0 = out + (size_t)gm * row_stride + (size_t)bz * OUTF + gn;
            float* p1 = p0 + 8 * row_stride;
            float2 v0 = { acc[mf][nf][0] + bv.x, acc[mf][nf][1] + bv.y };
            float2 v1 = { acc[mf][nf][2] + bv.x, acc[mf][nf][3] + bv.y };
            *(float2*)p0 = v0;
            *(float2*)p1 = v1;
        }
    }
#undef LOAD_A_FRAGS
#undef LOAD_B_FRAGS
#undef MMA_BURST
}

// ---------------- launch ----------------
extern "C" void kernel_launch(void* const* d_in, const int* in_sizes, int n_in,
                              void* d_out, int out_size) {
    const float *x = nullptr, *W = nullptr, *Bl = nullptr;
    for (int i = 0; i < n_in; i++) {
        long long s = in_sizes[i];
        if (s == (long long)NROWS * INF)          x  = (const float*)d_in[i];
        else if (s == 3LL * OUTF * INF)           W  = (const float*)d_in[i];
        else if (s == 3LL * OUTF)                 Bl = (const float*)d_in[i];
    }
    float* out = (float*)d_out;

    prep_w_kernel<<<(unsigned)(((size_t)OUTF * INF / 4 + 255) / 256), 256>>>(W);
    prep_x_kernel<<<(unsigned)(((size_t)NROWS * INF / 4 + 255) / 256), 256>>>(x);
    prep_b_kernel<<<(OUTF + 255) / 256, 256>>>(Bl);

    cudaFuncSetAttribute(gemm_kernel, cudaFuncAttributeMaxDynamicSharedMemorySize, SMEM_ALLOC);
    dim3 grid(OUTF / BN, NROWS / BM, 2);  // (32, 16, 2) = 1024 CTAs
    gemm_kernel<<<grid, 256, SMEM_ALLOC>>>(out);
}

// round 8
// speedup vs baseline: 1.1273x; 1.1077x over previous
#include <cuda_runtime.h>
#include <cuda_fp16.h>
#include <cstdint>

#define DEV __device__ __forceinline__

static constexpr int NROWS = 2048;
static constexpr int INF   = 4096;
static constexpr int OUTF  = 4096;

static constexpr int BM = 128, BN = 128, BK = 64;
static constexpr int STAGES = 3;                         // 3-deep ring
static constexpr int NIT = INF / BK;                     // 64
static constexpr int PITCH_H = 72;                       // halfs per smem row (64 + 8 pad)
static constexpr int PITCH_B = PITCH_H * 2;              // 144 bytes
static constexpr int A_BYTES = BM * PITCH_B;             // 18432
static constexpr int B_BYTES = BN * PITCH_B;             // 18432
static constexpr int STAGE_BYTES = A_BYTES + B_BYTES;    // 36864
static constexpr int SMEM_ALLOC = STAGES * STAGE_BYTES;  // 110592 (x2 CTAs = 216KB < 228KB)

// ---------------- scratch (no allocs allowed) ----------------
__device__ __align__(1024) __half g_wmean[(size_t)OUTF * INF];
__device__ __align__(1024) __half g_wvar [(size_t)OUTF * INF];
__device__ __align__(1024) __half g_xh   [(size_t)NROWS * INF];
__device__ __align__(1024) __half g_x2h  [(size_t)NROWS * INF];
__device__ float g_bmean[OUTF];
__device__ float g_bvar [OUTF];

// ---------------- PTX helpers ----------------
DEV uint32_t smem_u32(const void* p) {
    uint32_t a;
    asm("{ .reg .u64 t; cvta.to.shared.u64 t, %1; cvt.u32.u64 %0, t; }" : "=r"(a) : "l"(p));
    return a;
}
DEV void cp16(uint32_t saddr, const void* g) {
    asm volatile("cp.async.cg.shared.global [%0], [%1], 16;" :: "r"(saddr), "l"(g) : "memory");
}
DEV void ldm_x4(uint32_t* r, uint32_t addr) {
    asm volatile("ldmatrix.sync.aligned.m8n8.x4.shared.b16 {%0,%1,%2,%3}, [%4];"
                 : "=r"(r[0]), "=r"(r[1]), "=r"(r[2]), "=r"(r[3]) : "r"(addr));
}
DEV void mma16816(float* c, const uint32_t* a, uint32_t b0, uint32_t b1) {
    asm volatile(
        "mma.sync.aligned.m16n8k16.row.col.f32.f16.f16.f32 "
        "{%0,%1,%2,%3}, {%4,%5,%6,%7}, {%8,%9}, {%0,%1,%2,%3};"
        : "+f"(c[0]), "+f"(c[1]), "+f"(c[2]), "+f"(c[3])
        : "r"(a[0]), "r"(a[1]), "r"(a[2]), "r"(a[3]), "r"(b0), "r"(b1));
}

// ---------------- preprocessing ----------------
DEV void moments(float l0, float l1, float l2, float& mean, float& var) {
    float e0 = __expf(l0), e1 = __expf(l1), e2 = __expf(l2);
    float inv = 1.0f / (e0 + e1 + e2);
    float m  = (e2 - e0) * inv;
    float sq = (e2 + e0) * inv;
    mean = m;
    var  = sq - m * m;
}

__global__ void prep_w_kernel(const float* __restrict__ W) {
    const size_t P = (size_t)OUTF * INF;
    size_t i = ((size_t)blockIdx.x * blockDim.x + threadIdx.x) * 4;
    if (i >= P) return;
    float4 a = *(const float4*)(W + i);
    float4 b = *(const float4*)(W + P + i);
    float4 c = *(const float4*)(W + 2 * P + i);
    float m[4], v[4];
    moments(a.x, b.x, c.x, m[0], v[0]);
    moments(a.y, b.y, c.y, m[1], v[1]);
    moments(a.z, b.z, c.z, m[2], v[2]);
    moments(a.w, b.w, c.w, m[3], v[3]);
    __half2* pm = (__half2*)(g_wmean + i);
    pm[0] = __floats2half2_rn(m[0], m[1]);
    pm[1] = __floats2half2_rn(m[2], m[3]);
    __half2* pv = (__half2*)(g_wvar + i);
    pv[0] = __floats2half2_rn(v[0], v[1]);
    pv[1] = __floats2half2_rn(v[2], v[3]);
}

__global__ void prep_x_kernel(const float* __restrict__ x) {
    const size_t P = (size_t)NROWS * INF;
    size_t i = ((size_t)blockIdx.x * blockDim.x + threadIdx.x) * 4;
    if (i >= P) return;
    float4 a = *(const float4*)(x + i);
    __half2* ph = (__half2*)(g_xh + i);
    ph[0] = __floats2half2_rn(a.x, a.y);
    ph[1] = __floats2half2_rn(a.z, a.w);
    __half2* p2 = (__half2*)(g_x2h + i);
    p2[0] = __floats2half2_rn(a.x * a.x, a.y * a.y);
    p2[1] = __floats2half2_rn(a.z * a.z, a.w * a.w);
}

__global__ void prep_b_kernel(const float* __restrict__ B) {
    int o = blockIdx.x * blockDim.x + threadIdx.x;
    if (o >= OUTF) return;
    float m, v;
    moments(B[o], B[OUTF + o], B[2 * OUTF + o], m, v);
    g_bmean[o] = m;
    g_bvar[o]  = v;
}

// ---------------- GEMM ----------------
DEV void load_stage(char* smem, const char* gA, const char* gB, int cc, int tid) {
    char* sa  = smem + (cc % STAGES) * STAGE_BYTES;
    char* sbt = sa + A_BYTES;
    const char* ga = gA + (size_t)cc * (BK * 2);
    const char* gb = gB + (size_t)cc * (BK * 2);
#pragma unroll
    for (int i = 0; i < 4; i++) {
        int idx = tid + i * 256;              // 0..1023 over (row, 16B-seg)
        int row = idx >> 3, seg = idx & 7;
        uint32_t so = (uint32_t)(row * PITCH_B + seg * 16);
        size_t   go = (size_t)row * (INF * 2) + (size_t)seg * 16;
        cp16(smem_u32(sa  + so), ga + go);
        cp16(smem_u32(sbt + so), gb + go);
    }
}

__global__ void __launch_bounds__(256, 2)
gemm_kernel(float* __restrict__ out) {
    extern __shared__ char smem[];

    const int tid  = threadIdx.x;
    const int wid  = tid >> 5, lane = tid & 31;
    const int bn = blockIdx.x, bm = blockIdx.y, bz = blockIdx.z;

    const int wm = wid >> 1, wn = wid & 1;    // 4 x 2 warp grid
    const int m0 = wm * 32, n0 = wn * 64;     // warp tile 32 x 64

    const char* gA = (const char*)((bz == 0 ? g_xh    : g_x2h ) + (size_t)bm * BM * INF);
    const char* gB = (const char*)((bz == 0 ? g_wmean : g_wvar) + (size_t)bn * BN * INF);
    const float* bias = (bz == 0 ? g_bmean : g_bvar);

    float acc[2][8][4];
#pragma unroll
    for (int i = 0; i < 2; i++)
#pragma unroll
        for (int j = 0; j < 8; j++)
#pragma unroll
            for (int k = 0; k < 4; k++) acc[i][j][k] = 0.0f;

    // lane-dependent ldmatrix address offsets (bytes within a stage tile)
    const uint32_t a_off = (uint32_t)((m0 + (lane & 15)) * PITCH_B + (lane >> 4) * 16);
    const uint32_t b_off = (uint32_t)(A_BYTES + (n0 + (lane & 7) + ((lane >> 4) & 1) * 8) * PITCH_B
                                      + ((lane >> 3) & 1) * 16);
    const uint32_t smem_base = smem_u32(smem);

    // double-buffered register fragments
    uint32_t afr[2][2][4];
    uint32_t bfr[2][4][4];

#define LOAD_A_FRAGS(buf, stage_u, koff)                                          \
    _Pragma("unroll")                                                             \
    for (int mb = 0; mb < 2; mb++)                                                \
        ldm_x4(afr[buf][mb], (stage_u) + a_off + (uint32_t)(mb * 16 * PITCH_B + (koff)));
#define LOAD_B_FRAGS(buf, stage_u, koff)                                          \
    _Pragma("unroll")                                                             \
    for (int nb = 0; nb < 4; nb++)                                                \
        ldm_x4(bfr[buf][nb], (stage_u) + b_off + (uint32_t)(nb * 16 * PITCH_B + (koff)));
#define MMA_BURST(buf)                                                            \
    _Pragma("unroll")                                                             \
    for (int mb = 0; mb < 2; mb++)                                                \
        _Pragma("unroll")                                                         \
        for (int nb = 0; nb < 4; nb++) {                                          \
            mma16816(acc[mb][2 * nb],     afr[buf][mb], bfr[buf][nb][0], bfr[buf][nb][1]); \
            mma16816(acc[mb][2 * nb + 1], afr[buf][mb], bfr[buf][nb][2], bfr[buf][nb][3]); \
        }

    // prologue: stages 0,1 in flight (one commit group each)
    load_stage(smem, gA, gB, 0, tid);
    asm volatile("cp.async.commit_group;" ::: "memory");
    load_stage(smem, gA, gB, 1, tid);
    asm volatile("cp.async.commit_group;" ::: "memory");
    asm volatile("cp.async.wait_group 1;" ::: "memory");   // stage 0 resident
    __syncthreads();

    // buf0 <- stage 0, k-step 0
    LOAD_A_FRAGS(0, smem_base, 0)
    LOAD_B_FRAGS(0, smem_base, 0)

#pragma unroll 1
    for (int it = 0; it < NIT; it++) {
        const uint32_t su = smem_base + (uint32_t)((it % STAGES) * STAGE_BYTES);
        const uint32_t nu = smem_base + (uint32_t)(((it + 1) % STAGES) * STAGE_BYTES);

        // k1 -> buf1 ; MMA k0 (buf0)
        LOAD_A_FRAGS(1, su, 32)
        LOAD_B_FRAGS(1, su, 32)
        MMA_BURST(0)

        // k2 -> buf0 ; MMA k1 (buf1)
        LOAD_A_FRAGS(0, su, 64)
        LOAD_B_FRAGS(0, su, 64)
        MMA_BURST(1)

        // k3 -> buf1 ; MMA k2 (buf0)
        LOAD_A_FRAGS(1, su, 96)
        LOAD_B_FRAGS(1, su, 96)
        MMA_BURST(0)

        // refill slot (it+2)%3 == (it-1)%3: stage it-1's last reads were in
        // iter it-1 before that iter's sync -> safe to write now (R2 pattern).
        const int cc = it + 2;
        if (cc < NIT) load_stage(smem, gA, gB, cc, tid);
        asm volatile("cp.async.commit_group;" ::: "memory");
        // all but newest group done -> stage it+1 resident and visible
        asm volatile("cp.async.wait_group 1;" ::: "memory");
        __syncthreads();

        // next stage k0 -> buf0 (tail iteration reads stale smem, unused)
        LOAD_A_FRAGS(0, nu, 0)
        LOAD_B_FRAGS(0, nu, 0)
        // MMA k3 (buf1) — operands loaded pre-wait; drains across next
        // iteration's front-end work.
        MMA_BURST(1)
    }

    // epilogue: direct float2 stores with bias
    const int qr = lane >> 2, qc = lane & 3;
    const size_t row_stride = 2 * (size_t)OUTF;
#pragma unroll
    for (int mf = 0; mf < 2; mf++) {
        const int gm = bm * BM + m0 + mf * 16 + qr;
#pragma unroll
        for (int nf = 0; nf < 8; nf++) {
            const int gn = bn * BN + n0 + nf * 8 + qc * 2;
            const float2 bv = *(const float2*)(bias + gn);
            float* p0 = out + (size_t)gm * row_stride + (size_t)bz * OUTF + gn;
            float* p1 = p0 + 8 * row_stride;
            float2 v0 = { acc[mf][nf][0] + bv.x, acc[mf][nf][1] + bv.y };
            float2 v1 = { acc[mf][nf][2] + bv.x, acc[mf][nf][3] + bv.y };
            *(float2*)p0 = v0;
            *(float2*)p1 = v1;
        }
    }
#undef LOAD_A_FRAGS
#undef LOAD_B_FRAGS
#undef MMA_BURST
}

// ---------------- launch ----------------
extern "C" void kernel_launch(void* const* d_in, const int* in_sizes, int n_in,
                              void* d_out, int out_size) {
    const float *x = nullptr, *W = nullptr, *Bl = nullptr;
    for (int i = 0; i < n_in; i++) {
        long long s = in_sizes[i];
        if (s == (long long)NROWS * INF)          x  = (const float*)d_in[i];
        else if (s == 3LL * OUTF * INF)           W  = (const float*)d_in[i];
        else if (s == 3LL * OUTF)                 Bl = (const float*)d_in[i];
    }
    float* out = (float*)d_out;

    prep_w_kernel<<<(unsigned)(((size_t)OUTF * INF / 4 + 255) / 256), 256>>>(W);
    prep_x_kernel<<<(unsigned)(((size_t)NROWS * INF / 4 + 255) / 256), 256>>>(x);
    prep_b_kernel<<<(OUTF + 255) / 256, 256>>>(Bl);

    cudaFuncSetAttribute(gemm_kernel, cudaFuncAttributeMaxDynamicSharedMemorySize, SMEM_ALLOC);
    dim3 grid(OUTF / BN, NROWS / BM, 2);  // (32, 16, 2) = 1024 CTAs
    gemm_kernel<<<grid, 256, SMEM_ALLOC>>>(out);
}